// round 2
// baseline (speedup 1.0000x reference)
#include <cuda_runtime.h>

#define EMB 512
#define ROW 1024          // 2*EMB floats per head/tail row
#define THREADS 128       // 4 warps; each thread owns 4 floats of each half-vector

__device__ __forceinline__ float dot4(float4 a, float4 b) {
    return a.x * b.x + a.y * b.y + a.z * b.z + a.w * b.w;
}

__global__ __launch_bounds__(THREADS, 16)
void interht_kernel(const float* __restrict__ head,
                    const float* __restrict__ tail,
                    const float* __restrict__ rel_emb,
                    const int*   __restrict__ rel_id,
                    float*       __restrict__ out)
{
    const int row = blockIdx.x;
    const int t   = threadIdx.x;          // 0..127
    const int lane = t & 31;
    const int warp = t >> 5;

    // Row pointers (float4 view). main half = indices [0,128), aux = [128,256).
    const float4* h4 = reinterpret_cast<const float4*>(head + (size_t)row * ROW);
    const float4* t4 = reinterpret_cast<const float4*>(tail + (size_t)row * ROW);

    float4 hm = h4[t];
    float4 ha = h4[t + 128];
    float4 tm = t4[t];
    float4 ta = t4[t + 128];

    // ---- Phase 1: four squared-norm partial sums, reduced together ----
    float s0 = dot4(hm, hm);
    float s1 = dot4(ha, ha);
    float s2 = dot4(tm, tm);
    float s3 = dot4(ta, ta);

    #pragma unroll
    for (int o = 16; o > 0; o >>= 1) {
        s0 += __shfl_xor_sync(0xffffffffu, s0, o);
        s1 += __shfl_xor_sync(0xffffffffu, s1, o);
        s2 += __shfl_xor_sync(0xffffffffu, s2, o);
        s3 += __shfl_xor_sync(0xffffffffu, s3, o);
    }

    __shared__ float red[4][4];           // [warp][which-sum]
    if (lane == 0) {
        red[warp][0] = s0;
        red[warp][1] = s1;
        red[warp][2] = s2;
        red[warp][3] = s3;
    }
    __syncthreads();

    const float n_hm = red[0][0] + red[1][0] + red[2][0] + red[3][0];
    const float n_ha = red[0][1] + red[1][1] + red[2][1] + red[3][1];
    const float n_tm = red[0][2] + red[1][2] + red[2][2] + red[3][2];
    const float n_ta = red[0][3] + red[1][3] + red[2][3] + red[3][3];

    const float inv_hm = 1.0f / fmaxf(sqrtf(n_hm), 1e-12f);
    const float inv_ha = 1.0f / fmaxf(sqrtf(n_ha), 1e-12f);
    const float inv_tm = 1.0f / fmaxf(sqrtf(n_tm), 1e-12f);
    const float inv_ta = 1.0f / fmaxf(sqrtf(n_ta), 1e-12f);

    // ---- Relation gather (L2-resident table; uniform per block) ----
    const int rid = rel_id[row];
    const float4 rv = reinterpret_cast<const float4*>(rel_emb + (size_t)rid * EMB)[t];

    // ---- Phase 2: d = hm_n*(ta_n+1) + rel - tm_n*(ha_n+1); accumulate d^2 ----
    float acc = 0.0f;
    {
        float a, b, d;
        a = hm.x * inv_hm; b = ta.x * inv_ta + 1.0f;
        d = a * b + rv.x - (tm.x * inv_tm) * (ha.x * inv_ha + 1.0f);
        acc += d * d;
        a = hm.y * inv_hm; b = ta.y * inv_ta + 1.0f;
        d = a * b + rv.y - (tm.y * inv_tm) * (ha.y * inv_ha + 1.0f);
        acc += d * d;
        a = hm.z * inv_hm; b = ta.z * inv_ta + 1.0f;
        d = a * b + rv.z - (tm.z * inv_tm) * (ha.z * inv_ha + 1.0f);
        acc += d * d;
        a = hm.w * inv_hm; b = ta.w * inv_ta + 1.0f;
        d = a * b + rv.w - (tm.w * inv_tm) * (ha.w * inv_ha + 1.0f);
        acc += d * d;
    }

    #pragma unroll
    for (int o = 16; o > 0; o >>= 1)
        acc += __shfl_xor_sync(0xffffffffu, acc, o);

    __shared__ float red2[4];
    if (lane == 0) red2[warp] = acc;
    __syncthreads();

    if (t == 0) {
        const float total = red2[0] + red2[1] + red2[2] + red2[3];
        out[row] = -sqrtf(total);
    }
}

extern "C" void kernel_launch(void* const* d_in, const int* in_sizes, int n_in,
                              void* d_out, int out_size)
{
    const float* head    = (const float*)d_in[0];
    const float* tail    = (const float*)d_in[1];
    const float* rel_emb = (const float*)d_in[2];
    const int*   rel_id  = (const int*)d_in[3];
    float*       out     = (float*)d_out;

    const int batch = out_size;           // 131072 rows
    interht_kernel<<<batch, THREADS>>>(head, tail, rel_emb, rel_id, out);
}

// round 3
// speedup vs baseline: 1.0911x; 1.0911x over previous
#include <cuda_runtime.h>

#define EMB 512
#define ROW 1024           // 2*EMB floats per head/tail row
#define WPB 8              // warps (rows) per block
#define THREADS (WPB * 32)

__device__ __forceinline__ float dot4(float4 a, float4 b) {
    return a.x * b.x + a.y * b.y + a.z * b.z + a.w * b.w;
}

__global__ __launch_bounds__(THREADS)
void interht_kernel(const float* __restrict__ head,
                    const float* __restrict__ tail,
                    const float* __restrict__ rel_emb,
                    const int*   __restrict__ rel_id,
                    float*       __restrict__ out,
                    int batch)
{
    const int lane = threadIdx.x & 31;
    const int warp = threadIdx.x >> 5;
    const int row  = blockIdx.x * WPB + warp;
    if (row >= batch) return;

    const float4* h4 = reinterpret_cast<const float4*>(head + (size_t)row * ROW);
    const float4* t4 = reinterpret_cast<const float4*>(tail + (size_t)row * ROW);

    // Relation id + row pointer first so the gather loads join the batch.
    const int rid = __ldg(rel_id + row);
    const float4* r4 = reinterpret_cast<const float4*>(rel_emb + (size_t)rid * EMB);

    // ---- Issue all 20 loads up front (16 streaming + 4 L2-hit gather) ----
    float4 hm[4], ha[4], tm[4], ta[4], rv[4];
    #pragma unroll
    for (int i = 0; i < 4; i++) hm[i] = __ldcs(h4 + lane + 32 * i);
    #pragma unroll
    for (int i = 0; i < 4; i++) ha[i] = __ldcs(h4 + 128 + lane + 32 * i);
    #pragma unroll
    for (int i = 0; i < 4; i++) tm[i] = __ldcs(t4 + lane + 32 * i);
    #pragma unroll
    for (int i = 0; i < 4; i++) ta[i] = __ldcs(t4 + 128 + lane + 32 * i);
    #pragma unroll
    for (int i = 0; i < 4; i++) rv[i] = __ldg(r4 + lane + 32 * i);

    // ---- Phase 1: four squared norms, reduced with warp shuffles only ----
    float s0 = 0.f, s1 = 0.f, s2 = 0.f, s3 = 0.f;
    #pragma unroll
    for (int i = 0; i < 4; i++) {
        s0 += dot4(hm[i], hm[i]);
        s1 += dot4(ha[i], ha[i]);
        s2 += dot4(tm[i], tm[i]);
        s3 += dot4(ta[i], ta[i]);
    }
    #pragma unroll
    for (int o = 16; o > 0; o >>= 1) {
        s0 += __shfl_xor_sync(0xffffffffu, s0, o);
        s1 += __shfl_xor_sync(0xffffffffu, s1, o);
        s2 += __shfl_xor_sync(0xffffffffu, s2, o);
        s3 += __shfl_xor_sync(0xffffffffu, s3, o);
    }

    const float inv_hm = 1.0f / fmaxf(sqrtf(s0), 1e-12f);
    const float inv_ha = 1.0f / fmaxf(sqrtf(s1), 1e-12f);
    const float inv_tm = 1.0f / fmaxf(sqrtf(s2), 1e-12f);
    const float inv_ta = 1.0f / fmaxf(sqrtf(s3), 1e-12f);

    // ---- Phase 2: d = hm_n*(ta_n+1) + rel - tm_n*(ha_n+1); accumulate d^2 ----
    float acc = 0.0f;
    #pragma unroll
    for (int i = 0; i < 4; i++) {
        float d;
        d = (hm[i].x * inv_hm) * (ta[i].x * inv_ta + 1.0f) + rv[i].x
          - (tm[i].x * inv_tm) * (ha[i].x * inv_ha + 1.0f);
        acc += d * d;
        d = (hm[i].y * inv_hm) * (ta[i].y * inv_ta + 1.0f) + rv[i].y
          - (tm[i].y * inv_tm) * (ha[i].y * inv_ha + 1.0f);
        acc += d * d;
        d = (hm[i].z * inv_hm) * (ta[i].z * inv_ta + 1.0f) + rv[i].z
          - (tm[i].z * inv_tm) * (ha[i].z * inv_ha + 1.0f);
        acc += d * d;
        d = (hm[i].w * inv_hm) * (ta[i].w * inv_ta + 1.0f) + rv[i].w
          - (tm[i].w * inv_tm) * (ha[i].w * inv_ha + 1.0f);
        acc += d * d;
    }

    #pragma unroll
    for (int o = 16; o > 0; o >>= 1)
        acc += __shfl_xor_sync(0xffffffffu, acc, o);

    if (lane == 0)
        out[row] = -sqrtf(acc);
}

extern "C" void kernel_launch(void* const* d_in, const int* in_sizes, int n_in,
                              void* d_out, int out_size)
{
    const float* head    = (const float*)d_in[0];
    const float* tail    = (const float*)d_in[1];
    const float* rel_emb = (const float*)d_in[2];
    const int*   rel_id  = (const int*)d_in[3];
    float*       out     = (float*)d_out;

    const int batch = out_size;                    // 131072 rows
    const int grid  = (batch + WPB - 1) / WPB;
    interht_kernel<<<grid, THREADS>>>(head, tail, rel_emb, rel_id, out, batch);
}

// round 4
// speedup vs baseline: 1.0928x; 1.0016x over previous
#include <cuda_runtime.h>

#define EMB 512
#define ROW 1024           // 2*EMB floats per head/tail row
#define WPB 8              // warps (rows) per block
#define THREADS (WPB * 32)

__device__ __forceinline__ float dot4(float4 a, float4 b) {
    return a.x * b.x + a.y * b.y + a.z * b.z + a.w * b.w;
}

__global__ __launch_bounds__(THREADS)
void interht_kernel(const float* __restrict__ head,
                    const float* __restrict__ tail,
                    const float* __restrict__ rel_emb,
                    const int*   __restrict__ rel_id,
                    float*       __restrict__ out,
                    int batch)
{
    const int lane = threadIdx.x & 31;
    const int warp = threadIdx.x >> 5;
    const int row  = blockIdx.x * WPB + warp;
    if (row >= batch) return;

    const float4* h4 = reinterpret_cast<const float4*>(head + (size_t)row * ROW);
    const float4* t4 = reinterpret_cast<const float4*>(tail + (size_t)row * ROW);

    // Relation id + row pointer first so the gather loads join the batch.
    const int rid = __ldg(rel_id + row);
    const float4* r4 = reinterpret_cast<const float4*>(rel_emb + (size_t)rid * EMB);

    // ---- Issue all 20 loads up front (16 streaming + 4 L2-hit gather) ----
    float4 hm[4], ha[4], tm[4], ta[4], rv[4];
    #pragma unroll
    for (int i = 0; i < 4; i++) hm[i] = __ldcs(h4 + lane + 32 * i);
    #pragma unroll
    for (int i = 0; i < 4; i++) ha[i] = __ldcs(h4 + 128 + lane + 32 * i);
    #pragma unroll
    for (int i = 0; i < 4; i++) tm[i] = __ldcs(t4 + lane + 32 * i);
    #pragma unroll
    for (int i = 0; i < 4; i++) ta[i] = __ldcs(t4 + 128 + lane + 32 * i);
    #pragma unroll
    for (int i = 0; i < 4; i++) rv[i] = __ldg(r4 + lane + 32 * i);

    // ---- Phase 1: four squared norms, reduced with warp shuffles only ----
    float s0 = 0.f, s1 = 0.f, s2 = 0.f, s3 = 0.f;
    #pragma unroll
    for (int i = 0; i < 4; i++) {
        s0 += dot4(hm[i], hm[i]);
        s1 += dot4(ha[i], ha[i]);
        s2 += dot4(tm[i], tm[i]);
        s3 += dot4(ta[i], ta[i]);
    }
    #pragma unroll
    for (int o = 16; o > 0; o >>= 1) {
        s0 += __shfl_xor_sync(0xffffffffu, s0, o);
        s1 += __shfl_xor_sync(0xffffffffu, s1, o);
        s2 += __shfl_xor_sync(0xffffffffu, s2, o);
        s3 += __shfl_xor_sync(0xffffffffu, s3, o);
    }

    const float inv_hm = 1.0f / fmaxf(sqrtf(s0), 1e-12f);
    const float inv_ha = 1.0f / fmaxf(sqrtf(s1), 1e-12f);
    const float inv_tm = 1.0f / fmaxf(sqrtf(s2), 1e-12f);
    const float inv_ta = 1.0f / fmaxf(sqrtf(s3), 1e-12f);

    // ---- Phase 2: d = hm_n*(ta_n+1) + rel - tm_n*(ha_n+1); accumulate d^2 ----
    float acc = 0.0f;
    #pragma unroll
    for (int i = 0; i < 4; i++) {
        float d;
        d = (hm[i].x * inv_hm) * (ta[i].x * inv_ta + 1.0f) + rv[i].x
          - (tm[i].x * inv_tm) * (ha[i].x * inv_ha + 1.0f);
        acc += d * d;
        d = (hm[i].y * inv_hm) * (ta[i].y * inv_ta + 1.0f) + rv[i].y
          - (tm[i].y * inv_tm) * (ha[i].y * inv_ha + 1.0f);
        acc += d * d;
        d = (hm[i].z * inv_hm) * (ta[i].z * inv_ta + 1.0f) + rv[i].z
          - (tm[i].z * inv_tm) * (ha[i].z * inv_ha + 1.0f);
        acc += d * d;
        d = (hm[i].w * inv_hm) * (ta[i].w * inv_ta + 1.0f) + rv[i].w
          - (tm[i].w * inv_tm) * (ha[i].w * inv_ha + 1.0f);
        acc += d * d;
    }

    #pragma unroll
    for (int o = 16; o > 0; o >>= 1)
        acc += __shfl_xor_sync(0xffffffffu, acc, o);

    if (lane == 0)
        out[row] = -sqrtf(acc);
}

extern "C" void kernel_launch(void* const* d_in, const int* in_sizes, int n_in,
                              void* d_out, int out_size)
{
    const float* head    = (const float*)d_in[0];
    const float* tail    = (const float*)d_in[1];
    const float* rel_emb = (const float*)d_in[2];
    const int*   rel_id  = (const int*)d_in[3];
    float*       out     = (float*)d_out;

    const int batch = out_size;                    // 131072 rows
    const int grid  = (batch + WPB - 1) / WPB;
    interht_kernel<<<grid, THREADS>>>(head, tail, rel_emb, rel_id, out, batch);
}

// round 5
// speedup vs baseline: 1.0946x; 1.0016x over previous
#include <cuda_runtime.h>

#define EMB 512
#define ROW 1024           // 2*EMB floats per head/tail row
#define WPB 8              // warps (rows) per block
#define THREADS (WPB * 32)

__device__ __forceinline__ float dot4(float4 a, float4 b) {
    return a.x * b.x + a.y * b.y + a.z * b.z + a.w * b.w;
}

__global__ __launch_bounds__(THREADS)
void interht_kernel(const float* __restrict__ head,
                    const float* __restrict__ tail,
                    const float* __restrict__ rel_emb,
                    const int*   __restrict__ rel_id,
                    float*       __restrict__ out,
                    int batch)
{
    const int lane = threadIdx.x & 31;
    const int warp = threadIdx.x >> 5;
    const int row  = blockIdx.x * WPB + warp;
    if (row >= batch) return;

    const float4* h4 = reinterpret_cast<const float4*>(head + (size_t)row * ROW);
    const float4* t4 = reinterpret_cast<const float4*>(tail + (size_t)row * ROW);

    // Relation id + row pointer first so the gather loads join the batch.
    const int rid = __ldg(rel_id + row);
    const float4* r4 = reinterpret_cast<const float4*>(rel_emb + (size_t)rid * EMB);

    // ---- Issue all 20 loads up front (16 streaming + 4 L2-hit gather) ----
    float4 hm[4], ha[4], tm[4], ta[4], rv[4];
    #pragma unroll
    for (int i = 0; i < 4; i++) hm[i] = __ldcs(h4 + lane + 32 * i);
    #pragma unroll
    for (int i = 0; i < 4; i++) ha[i] = __ldcs(h4 + 128 + lane + 32 * i);
    #pragma unroll
    for (int i = 0; i < 4; i++) tm[i] = __ldcs(t4 + lane + 32 * i);
    #pragma unroll
    for (int i = 0; i < 4; i++) ta[i] = __ldcs(t4 + 128 + lane + 32 * i);
    #pragma unroll
    for (int i = 0; i < 4; i++) rv[i] = __ldg(r4 + lane + 32 * i);

    // ---- Phase 1: four squared norms, reduced with warp shuffles only ----
    float s0 = 0.f, s1 = 0.f, s2 = 0.f, s3 = 0.f;
    #pragma unroll
    for (int i = 0; i < 4; i++) {
        s0 += dot4(hm[i], hm[i]);
        s1 += dot4(ha[i], ha[i]);
        s2 += dot4(tm[i], tm[i]);
        s3 += dot4(ta[i], ta[i]);
    }
    #pragma unroll
    for (int o = 16; o > 0; o >>= 1) {
        s0 += __shfl_xor_sync(0xffffffffu, s0, o);
        s1 += __shfl_xor_sync(0xffffffffu, s1, o);
        s2 += __shfl_xor_sync(0xffffffffu, s2, o);
        s3 += __shfl_xor_sync(0xffffffffu, s3, o);
    }

    const float inv_hm = 1.0f / fmaxf(sqrtf(s0), 1e-12f);
    const float inv_ha = 1.0f / fmaxf(sqrtf(s1), 1e-12f);
    const float inv_tm = 1.0f / fmaxf(sqrtf(s2), 1e-12f);
    const float inv_ta = 1.0f / fmaxf(sqrtf(s3), 1e-12f);

    // ---- Phase 2: d = hm_n*(ta_n+1) + rel - tm_n*(ha_n+1); accumulate d^2 ----
    float acc = 0.0f;
    #pragma unroll
    for (int i = 0; i < 4; i++) {
        float d;
        d = (hm[i].x * inv_hm) * (ta[i].x * inv_ta + 1.0f) + rv[i].x
          - (tm[i].x * inv_tm) * (ha[i].x * inv_ha + 1.0f);
        acc += d * d;
        d = (hm[i].y * inv_hm) * (ta[i].y * inv_ta + 1.0f) + rv[i].y
          - (tm[i].y * inv_tm) * (ha[i].y * inv_ha + 1.0f);
        acc += d * d;
        d = (hm[i].z * inv_hm) * (ta[i].z * inv_ta + 1.0f) + rv[i].z
          - (tm[i].z * inv_tm) * (ha[i].z * inv_ha + 1.0f);
        acc += d * d;
        d = (hm[i].w * inv_hm) * (ta[i].w * inv_ta + 1.0f) + rv[i].w
          - (tm[i].w * inv_tm) * (ha[i].w * inv_ha + 1.0f);
        acc += d * d;
    }

    #pragma unroll
    for (int o = 16; o > 0; o >>= 1)
        acc += __shfl_xor_sync(0xffffffffu, acc, o);

    if (lane == 0)
        out[row] = -sqrtf(acc);
}

extern "C" void kernel_launch(void* const* d_in, const int* in_sizes, int n_in,
                              void* d_out, int out_size)
{
    const float* head    = (const float*)d_in[0];
    const float* tail    = (const float*)d_in[1];
    const float* rel_emb = (const float*)d_in[2];
    const int*   rel_id  = (const int*)d_in[3];
    float*       out     = (float*)d_out;

    const int batch = out_size;                    // 131072 rows
    const int grid  = (batch + WPB - 1) / WPB;
    interht_kernel<<<grid, THREADS>>>(head, tail, rel_emb, rel_id, out, batch);
}

// round 6
// speedup vs baseline: 1.0976x; 1.0028x over previous
#include <cuda_runtime.h>

#define EMB 512
#define ROW 1024           // 2*EMB floats per head/tail row
#define WPB 8              // warps (rows) per block
#define THREADS (WPB * 32)

__device__ __forceinline__ float dot4(float4 a, float4 b) {
    return a.x * b.x + a.y * b.y + a.z * b.z + a.w * b.w;
}

__global__ __launch_bounds__(THREADS)
void interht_kernel(const float* __restrict__ head,
                    const float* __restrict__ tail,
                    const float* __restrict__ rel_emb,
                    const int*   __restrict__ rel_id,
                    float*       __restrict__ out,
                    int batch)
{
    const int lane = threadIdx.x & 31;
    const int warp = threadIdx.x >> 5;
    const int row  = blockIdx.x * WPB + warp;
    if (row >= batch) return;

    const float4* h4 = reinterpret_cast<const float4*>(head + (size_t)row * ROW);
    const float4* t4 = reinterpret_cast<const float4*>(tail + (size_t)row * ROW);

    // Relation id + row pointer first so the gather loads join the batch.
    const int rid = __ldg(rel_id + row);
    const float4* r4 = reinterpret_cast<const float4*>(rel_emb + (size_t)rid * EMB);

    // ---- Issue all 20 loads up front (16 streaming + 4 L2-hit gather) ----
    float4 hm[4], ha[4], tm[4], ta[4], rv[4];
    #pragma unroll
    for (int i = 0; i < 4; i++) hm[i] = __ldcs(h4 + lane + 32 * i);
    #pragma unroll
    for (int i = 0; i < 4; i++) ha[i] = __ldcs(h4 + 128 + lane + 32 * i);
    #pragma unroll
    for (int i = 0; i < 4; i++) tm[i] = __ldcs(t4 + lane + 32 * i);
    #pragma unroll
    for (int i = 0; i < 4; i++) ta[i] = __ldcs(t4 + 128 + lane + 32 * i);
    #pragma unroll
    for (int i = 0; i < 4; i++) rv[i] = __ldg(r4 + lane + 32 * i);

    // ---- Phase 1: four squared norms, reduced with warp shuffles only ----
    float s0 = 0.f, s1 = 0.f, s2 = 0.f, s3 = 0.f;
    #pragma unroll
    for (int i = 0; i < 4; i++) {
        s0 += dot4(hm[i], hm[i]);
        s1 += dot4(ha[i], ha[i]);
        s2 += dot4(tm[i], tm[i]);
        s3 += dot4(ta[i], ta[i]);
    }
    #pragma unroll
    for (int o = 16; o > 0; o >>= 1) {
        s0 += __shfl_xor_sync(0xffffffffu, s0, o);
        s1 += __shfl_xor_sync(0xffffffffu, s1, o);
        s2 += __shfl_xor_sync(0xffffffffu, s2, o);
        s3 += __shfl_xor_sync(0xffffffffu, s3, o);
    }

    const float inv_hm = 1.0f / fmaxf(sqrtf(s0), 1e-12f);
    const float inv_ha = 1.0f / fmaxf(sqrtf(s1), 1e-12f);
    const float inv_tm = 1.0f / fmaxf(sqrtf(s2), 1e-12f);
    const float inv_ta = 1.0f / fmaxf(sqrtf(s3), 1e-12f);

    // ---- Phase 2: d = hm_n*(ta_n+1) + rel - tm_n*(ha_n+1); accumulate d^2 ----
    float acc = 0.0f;
    #pragma unroll
    for (int i = 0; i < 4; i++) {
        float d;
        d = (hm[i].x * inv_hm) * (ta[i].x * inv_ta + 1.0f) + rv[i].x
          - (tm[i].x * inv_tm) * (ha[i].x * inv_ha + 1.0f);
        acc += d * d;
        d = (hm[i].y * inv_hm) * (ta[i].y * inv_ta + 1.0f) + rv[i].y
          - (tm[i].y * inv_tm) * (ha[i].y * inv_ha + 1.0f);
        acc += d * d;
        d = (hm[i].z * inv_hm) * (ta[i].z * inv_ta + 1.0f) + rv[i].z
          - (tm[i].z * inv_tm) * (ha[i].z * inv_ha + 1.0f);
        acc += d * d;
        d = (hm[i].w * inv_hm) * (ta[i].w * inv_ta + 1.0f) + rv[i].w
          - (tm[i].w * inv_tm) * (ha[i].w * inv_ha + 1.0f);
        acc += d * d;
    }

    #pragma unroll
    for (int o = 16; o > 0; o >>= 1)
        acc += __shfl_xor_sync(0xffffffffu, acc, o);

    if (lane == 0)
        out[row] = -sqrtf(acc);
}

extern "C" void kernel_launch(void* const* d_in, const int* in_sizes, int n_in,
                              void* d_out, int out_size)
{
    const float* head    = (const float*)d_in[0];
    const float* tail    = (const float*)d_in[1];
    const float* rel_emb = (const float*)d_in[2];
    const int*   rel_id  = (const int*)d_in[3];
    float*       out     = (float*)d_out;

    const int batch = out_size;                    // 131072 rows
    const int grid  = (batch + WPB - 1) / WPB;
    interht_kernel<<<grid, THREADS>>>(head, tail, rel_emb, rel_id, out, batch);
}